// round 10
// baseline (speedup 1.0000x reference)
#include <cuda_runtime.h>
#include <cuda_bf16.h>
#include <cstdint>
#include <math.h>

// Problem constants
#define B_   4
#define S_   2048
#define D_   1024
#define H_   16
#define HD_  64
#define M_   (B_ * S_)   // 8192 rows
#define K_   1024
#define N_   1024

// ---------------------------------------------------------------------------
// Scratch (static __device__; allocation is forbidden)
// ---------------------------------------------------------------------------
__device__ __nv_bfloat16 g_qhi[(size_t)M_ * D_];
__device__ __nv_bfloat16 g_qlo[(size_t)M_ * D_];
__device__ __nv_bfloat16 g_khi[(size_t)M_ * D_];
__device__ __nv_bfloat16 g_klo[(size_t)M_ * D_];
__device__ __nv_bfloat16 g_vhi[(size_t)M_ * D_];
__device__ __nv_bfloat16 g_vlo[(size_t)M_ * D_];
__device__ __nv_bfloat16 g_ohi[(size_t)M_ * D_];
__device__ __nv_bfloat16 g_olo[(size_t)M_ * D_];
__device__ __nv_bfloat16 g_xhi[(size_t)M_ * D_];
__device__ __nv_bfloat16 g_xlo[(size_t)M_ * D_];
// transposed split weights: [4][N][K]  (order: q,k,v,o)
__device__ __nv_bfloat16 g_wThi[(size_t)4 * N_ * K_];
__device__ __nv_bfloat16 g_wTlo[(size_t)4 * N_ * K_];

// ---------------------------------------------------------------------------
// helpers
// ---------------------------------------------------------------------------
__device__ __forceinline__ uint32_t smem_u32(const void* p) {
    uint32_t a;
    asm("{ .reg .u64 t; cvta.to.shared.u64 t, %1; cvt.u32.u64 %0, t; }"
        : "=r"(a) : "l"(p));
    return a;
}
__device__ __forceinline__ void cp_async16(uint32_t dst, const void* src) {
    asm volatile("cp.async.cg.shared.global [%0], [%1], 16;"
                 :: "r"(dst), "l"(src) : "memory");
}
__device__ __forceinline__ void cp_commit() {
    asm volatile("cp.async.commit_group;" ::: "memory");
}
template <int N>
__device__ __forceinline__ void cp_wait() {
    asm volatile("cp.async.wait_group %0;" :: "n"(N) : "memory");
}
__device__ __forceinline__ void ldm_x4(uint32_t (&r)[4], uint32_t addr) {
    asm volatile("ldmatrix.sync.aligned.m8n8.x4.shared.b16 {%0,%1,%2,%3}, [%4];"
                 : "=r"(r[0]), "=r"(r[1]), "=r"(r[2]), "=r"(r[3]) : "r"(addr));
}
__device__ __forceinline__ void ldm_x4_t(uint32_t (&r)[4], uint32_t addr) {
    asm volatile("ldmatrix.sync.aligned.m8n8.x4.trans.shared.b16 {%0,%1,%2,%3}, [%4];"
                 : "=r"(r[0]), "=r"(r[1]), "=r"(r[2]), "=r"(r[3]) : "r"(addr));
}
__device__ __forceinline__ void mma16816(float* d, const uint32_t* a, const uint32_t* b) {
    asm volatile(
        "mma.sync.aligned.m16n8k16.row.col.f32.bf16.bf16.f32 "
        "{%0,%1,%2,%3}, {%4,%5,%6,%7}, {%8,%9}, {%0,%1,%2,%3};"
        : "+f"(d[0]), "+f"(d[1]), "+f"(d[2]), "+f"(d[3])
        : "r"(a[0]), "r"(a[1]), "r"(a[2]), "r"(a[3]), "r"(b[0]), "r"(b[1]));
}
__device__ __forceinline__ float ex2(float x) {
    float y;
    asm("ex2.approx.f32 %0, %1;" : "=f"(y) : "f"(x));
    return y;
}
__device__ __forceinline__ uint32_t packbf(float lo, float hi) {
    uint32_t d;
    asm("cvt.rn.bf16x2.f32 %0, %1, %2;" : "=r"(d) : "f"(hi), "f"(lo));
    return d;
}
__device__ __forceinline__ float bflowf(uint32_t p)  { return __uint_as_float(p << 16); }
__device__ __forceinline__ float bfhighf(uint32_t p) { return __uint_as_float(p & 0xFFFF0000u); }

// ---------------------------------------------------------------------------
// Fused prep: blocks [0, 8192) split x; blocks [8192, 12288) split+transpose W.
// ---------------------------------------------------------------------------
__global__ __launch_bounds__(256)
void prep_kernel(const float* __restrict__ x,
                 __nv_bfloat16* __restrict__ xhi,
                 __nv_bfloat16* __restrict__ xlo,
                 const float* __restrict__ Wq,
                 const float* __restrict__ Wk,
                 const float* __restrict__ Wv,
                 const float* __restrict__ Wo,
                 __nv_bfloat16* __restrict__ wThi,
                 __nv_bfloat16* __restrict__ wTlo)
{
    const int bx = blockIdx.x;
    if (bx < 8192) {
        int i = bx * 256 + threadIdx.x;
        float4 v = ((const float4*)x)[i];
        uint32_t h0 = packbf(v.x, v.y);
        uint32_t h1 = packbf(v.z, v.w);
        uint32_t l0 = packbf(v.x - bflowf(h0), v.y - bfhighf(h0));
        uint32_t l1 = packbf(v.z - bflowf(h1), v.w - bfhighf(h1));
        ((uint32_t*)xhi)[i * 2 + 0] = h0;
        ((uint32_t*)xhi)[i * 2 + 1] = h1;
        ((uint32_t*)xlo)[i * 2 + 0] = l0;
        ((uint32_t*)xlo)[i * 2 + 1] = l1;
    } else {
        __shared__ float t[32][33];
        const int u    = bx - 8192;
        const int widx = u >> 10;
        const int tile = u & 1023;
        const int n0 = (tile & 31) * 32;
        const int k0 = (tile >> 5) * 32;
        const float* W = (widx == 0) ? Wq : (widx == 1) ? Wk : (widx == 2) ? Wv : Wo;
        __nv_bfloat16* hiT = wThi + (size_t)widx * N_ * K_;
        __nv_bfloat16* loT = wTlo + (size_t)widx * N_ * K_;
        const int tx = threadIdx.x & 31;
        const int ty = threadIdx.x >> 5;
        #pragma unroll
        for (int i = 0; i < 4; i++) {
            int kr = ty + i * 8;
            t[kr][tx] = W[(size_t)(k0 + kr) * N_ + n0 + tx];
        }
        __syncthreads();
        #pragma unroll
        for (int i = 0; i < 4; i++) {
            int nr = ty + i * 8;
            float v = t[tx][nr];
            __nv_bfloat16 h = __float2bfloat16_rn(v);
            size_t idx = (size_t)(n0 + nr) * K_ + k0 + tx;
            hiT[idx] = h;
            loT[idx] = __float2bfloat16_rn(v - __bfloat162float(h));
        }
    }
}

// ---------------------------------------------------------------------------
// HMMA split-bf16 GEMM core (3-stage, 1 barrier/chunk). Per-tile body.
// ---------------------------------------------------------------------------
#define GBK 32
static constexpr uint32_t TILEB  = 128 * GBK * 2;   // 8192
static constexpr uint32_t STAGEB = 4 * TILEB;       // 32768
#define GEMM_SMEM (3 * STAGEB)                      // 98304
#define GEMM_GRID 296                               // 2 CTAs/SM x 148 SMs

__device__ __forceinline__ uint32_t swz64(int r, int c) {
    return (uint32_t)(r * 64 + ((c ^ ((r >> 1) & 3)) << 4));
}

template <bool SPLIT_OUT>
__device__ __forceinline__
void gemm_core(const __nv_bfloat16* __restrict__ Ahi,
               const __nv_bfloat16* __restrict__ Alo,
               const __nv_bfloat16* __restrict__ BhiT,
               const __nv_bfloat16* __restrict__ BloT,
               const float* __restrict__ bias,
               float* __restrict__ C,
               __nv_bfloat16* __restrict__ Chi,
               __nv_bfloat16* __restrict__ Clo,
               float scale, int bm, int bn)
{
    extern __shared__ char gsm[];
    const uint32_t sb = smem_u32(gsm);
    const int tid = threadIdx.x;
    const int L   = tid & 31;
    const int wid = tid >> 5;
    const int warp_m = wid >> 2;
    const int warp_n = wid & 3;

    const int r0 = tid >> 2,         c0 = tid & 3;
    const int r1 = (tid + 256) >> 2, c1 = (tid + 256) & 3;
    const uint32_t d0 = swz64(r0, c0);
    const uint32_t d1 = swz64(r1, c1);

    const __nv_bfloat16* srcAhi0 = Ahi + (size_t)(bm + r0) * K_ + c0 * 8;
    const __nv_bfloat16* srcAlo0 = Alo + (size_t)(bm + r0) * K_ + c0 * 8;
    const __nv_bfloat16* srcBhi0 = BhiT + (size_t)(bn + r0) * K_ + c0 * 8;
    const __nv_bfloat16* srcBlo0 = BloT + (size_t)(bn + r0) * K_ + c0 * 8;
    const __nv_bfloat16* srcAhi1 = Ahi + (size_t)(bm + r1) * K_ + c1 * 8;
    const __nv_bfloat16* srcAlo1 = Alo + (size_t)(bm + r1) * K_ + c1 * 8;
    const __nv_bfloat16* srcBhi1 = BhiT + (size_t)(bn + r1) * K_ + c1 * 8;
    const __nv_bfloat16* srcBlo1 = BloT + (size_t)(bn + r1) * K_ + c1 * 8;

    const int a_mrow = (L & 7) | (((L >> 3) & 1) << 3);
    const int a_kc   = (L >> 4) & 1;
    const int b_nrow = (L & 7) | (((L >> 4) & 1) << 3);
    const int b_kc   = (L >> 3) & 1;

    float acc[4][4][4];
    #pragma unroll
    for (int mi = 0; mi < 4; mi++)
        #pragma unroll
        for (int ni = 0; ni < 4; ni++)
            #pragma unroll
            for (int j = 0; j < 4; j++)
                acc[mi][ni][j] = 0.0f;

    auto load_stage = [&](int ch, int st) {
        const int ko = ch * GBK;
        const uint32_t s = sb + st * STAGEB;
        cp_async16(s + d0,              srcAhi0 + ko);
        cp_async16(s + TILEB + d0,      srcAlo0 + ko);
        cp_async16(s + 2 * TILEB + d0,  srcBhi0 + ko);
        cp_async16(s + 3 * TILEB + d0,  srcBlo0 + ko);
        cp_async16(s + d1,              srcAhi1 + ko);
        cp_async16(s + TILEB + d1,      srcAlo1 + ko);
        cp_async16(s + 2 * TILEB + d1,  srcBhi1 + ko);
        cp_async16(s + 3 * TILEB + d1,  srcBlo1 + ko);
        cp_commit();
    };

    load_stage(0, 0);
    load_stage(1, 1);

    const int NCH = K_ / GBK;
    int st = 0;
    for (int ch = 0; ch < NCH; ch++) {
        if (ch + 1 < NCH) { cp_wait<1>(); } else { cp_wait<0>(); }
        __syncthreads();
        if (ch + 2 < NCH) {
            int st2 = st + 2; if (st2 >= 3) st2 -= 3;
            load_stage(ch + 2, st2);
        }

        const uint32_t s = sb + st * STAGEB;
        #pragma unroll
        for (int ks = 0; ks < 2; ks++) {
            uint32_t ahi[4][4], alo[4][4], bhi[2][4], blo[2][4];
            const int ca = ks * 2 + a_kc;
            #pragma unroll
            for (int mi = 0; mi < 4; mi++) {
                int r = warp_m * 64 + mi * 16 + a_mrow;
                uint32_t o = swz64(r, ca);
                ldm_x4(ahi[mi], s + o);
                ldm_x4(alo[mi], s + TILEB + o);
            }
            const int cb = ks * 2 + b_kc;
            #pragma unroll
            for (int j = 0; j < 2; j++) {
                int r = warp_n * 32 + j * 16 + b_nrow;
                uint32_t o = swz64(r, cb);
                ldm_x4(bhi[j], s + 2 * TILEB + o);
                ldm_x4(blo[j], s + 3 * TILEB + o);
            }
            #pragma unroll
            for (int mi = 0; mi < 4; mi++) {
                #pragma unroll
                for (int ni = 0; ni < 4; ni++) {
                    const uint32_t* bh = &bhi[ni >> 1][(ni & 1) * 2];
                    const uint32_t* bl = &blo[ni >> 1][(ni & 1) * 2];
                    mma16816(acc[mi][ni], ahi[mi], bh);
                    mma16816(acc[mi][ni], ahi[mi], bl);
                    mma16816(acc[mi][ni], alo[mi], bh);
                }
            }
        }
        st = st + 1; if (st >= 3) st = 0;
    }

    const int g  = L >> 2;
    const int tg = L & 3;
    #pragma unroll
    for (int mi = 0; mi < 4; mi++) {
        int row0 = bm + warp_m * 64 + mi * 16 + g;
        #pragma unroll
        for (int ni = 0; ni < 4; ni++) {
            int col = bn + warp_n * 32 + ni * 8 + tg * 2;
            float b0 = bias[col], b1 = bias[col + 1];
            float r00 = (acc[mi][ni][0] + b0) * scale;
            float r01 = (acc[mi][ni][1] + b1) * scale;
            float r10 = (acc[mi][ni][2] + b0) * scale;
            float r11 = (acc[mi][ni][3] + b1) * scale;
            if (SPLIT_OUT) {
                uint32_t h0 = packbf(r00, r01);
                uint32_t l0 = packbf(r00 - bflowf(h0), r01 - bfhighf(h0));
                uint32_t h1 = packbf(r10, r11);
                uint32_t l1 = packbf(r10 - bflowf(h1), r11 - bfhighf(h1));
                *(uint32_t*)&Chi[(size_t)row0 * N_ + col] = h0;
                *(uint32_t*)&Clo[(size_t)row0 * N_ + col] = l0;
                *(uint32_t*)&Chi[(size_t)(row0 + 8) * N_ + col] = h1;
                *(uint32_t*)&Clo[(size_t)(row0 + 8) * N_ + col] = l1;
            } else {
                float2 v0 = {r00, r01}, v1 = {r10, r11};
                *(float2*)&C[(size_t)row0 * N_ + col] = v0;
                *(float2*)&C[(size_t)(row0 + 8) * N_ + col] = v1;
            }
        }
    }
    __syncthreads();   // tile boundary: pipeline smem reuse safety
}

// Persistent fused Q/K/V projection: 1536 tiles over GEMM_GRID CTAs.
__global__ __launch_bounds__(256)
void gemm_qkv_kernel(const __nv_bfloat16* __restrict__ xhi,
                     const __nv_bfloat16* __restrict__ xlo,
                     const __nv_bfloat16* __restrict__ wThi,
                     const __nv_bfloat16* __restrict__ wTlo,
                     const float* __restrict__ bq,
                     const float* __restrict__ bk,
                     const float* __restrict__ bv,
                     __nv_bfloat16* __restrict__ qhi, __nv_bfloat16* __restrict__ qlo,
                     __nv_bfloat16* __restrict__ khi, __nv_bfloat16* __restrict__ klo,
                     __nv_bfloat16* __restrict__ vhi, __nv_bfloat16* __restrict__ vlo,
                     float qscale)
{
    const size_t WSZ = (size_t)N_ * K_;
    const int NT = 3 * 8 * (M_ / 128);   // 1536
    for (int t = blockIdx.x; t < NT; t += gridDim.x) {
        const int which = t % 3;
        const int rest  = t / 3;
        const int bn = (rest & 7) * 128;
        const int bm = (rest >> 3) * 128;

        const __nv_bfloat16* Bhi = wThi + (size_t)which * WSZ;
        const __nv_bfloat16* Blo = wTlo + (size_t)which * WSZ;
        const float* bias = (which == 0) ? bq : (which == 1) ? bk : bv;
        __nv_bfloat16* Chi = (which == 0) ? qhi : (which == 1) ? khi : vhi;
        __nv_bfloat16* Clo = (which == 0) ? qlo : (which == 1) ? klo : vlo;
        const float scale = (which == 0) ? qscale : 1.0f;

        gemm_core<true>(xhi, xlo, Bhi, Blo, bias, nullptr, Chi, Clo, scale, bm, bn);
    }
}

// Persistent output projection: 512 tiles.
__global__ __launch_bounds__(256)
void gemm_o_kernel(const __nv_bfloat16* __restrict__ ohi,
                   const __nv_bfloat16* __restrict__ olo,
                   const __nv_bfloat16* __restrict__ wThiO,
                   const __nv_bfloat16* __restrict__ wTloO,
                   const float* __restrict__ bo,
                   float* __restrict__ out)
{
    const int NT = 8 * (M_ / 128);       // 512
    for (int t = blockIdx.x; t < NT; t += gridDim.x) {
        const int bn = (t & 7) * 128;
        const int bm = (t >> 3) * 128;
        gemm_core<false>(ohi, olo, wThiO, wTloO, bo, out, nullptr, nullptr, 1.0f,
                         bm, bn);
    }
}

// ---------------------------------------------------------------------------
// Tensor-core causal flash attention, split-bf16, FIXED-MAX exp2 softmax.
// ---------------------------------------------------------------------------
#define AT_SMEM 65536
#define M_FIX 24.0f

__global__ __launch_bounds__(256, 1)
void attn_mma_kernel(const __nv_bfloat16* __restrict__ qhi,
                     const __nv_bfloat16* __restrict__ qlo,
                     const __nv_bfloat16* __restrict__ khi,
                     const __nv_bfloat16* __restrict__ klo,
                     const __nv_bfloat16* __restrict__ vhi,
                     const __nv_bfloat16* __restrict__ vlo,
                     __nv_bfloat16* __restrict__ ohi,
                     __nv_bfloat16* __restrict__ olo)
{
    extern __shared__ char sm[];
    const uint32_t sb = smem_u32(sm);
    const int tid = threadIdx.x;
    const int L   = tid & 31;
    const int w   = tid >> 5;
    const int bh  = blockIdx.y;
    const int b   = bh >> 4;
    const int h   = bh & 15;
    const int q0  = (int)(gridDim.x - 1 - blockIdx.x) * 128;

    #pragma unroll
    for (int i = 0; i < 4; i++) {
        int u = i * 256 + tid;
        int r = u >> 3;
        int c = u & 7;
        uint32_t d = sb + (uint32_t)(r * 128 + ((c ^ (r & 7)) << 4));
        size_t src = ((size_t)b * S_ + q0 + r) * D_ + h * HD_ + c * 8;
        cp_async16(d,         qhi + src);
        cp_async16(d + 16384, qlo + src);
    }
    cp_commit();
    cp_wait<0>();
    __syncthreads();

    const int a_mrow = (L & 7) | (((L >> 3) & 1) << 3);
    const int a_kc   = (L >> 4) & 1;
    uint32_t fqh[4][4], fql[4][4];
    #pragma unroll
    for (int ks = 0; ks < 4; ks++) {
        int r = w * 16 + a_mrow;
        int c = 2 * ks + a_kc;
        uint32_t addr = sb + (uint32_t)(r * 128 + ((c ^ (r & 7)) << 4));
        ldm_x4(fqh[ks], addr);
        ldm_x4(fql[ks], addr + 16384);
    }
    __syncthreads();

    const int b_nrow = (L & 7) | (((L >> 4) & 1) << 3);
    const int b_kc   = (L >> 3) & 1;
    const int vkrow  = L & 15;
    const int vdch   = (L >> 4) & 1;

    float accO[8][4];
    #pragma unroll
    for (int i = 0; i < 8; i++)
        #pragma unroll
        for (int j = 0; j < 4; j++) accO[i][j] = 0.0f;
    float lsum[2] = {0.0f, 0.0f};

    const size_t kvcol = (size_t)h * HD_;

    auto load_kv = [&](int j, int st) {
        uint32_t base = sb + (uint32_t)(st * 32768);
        size_t row0 = (size_t)b * S_ + j * 64;
        #pragma unroll
        for (int i = 0; i < 2; i++) {
            int u = i * 256 + tid;
            int r = u >> 3;
            int c = u & 7;
            uint32_t d = base + (uint32_t)(r * 128 + ((c ^ (r & 7)) << 4));
            size_t src = (row0 + r) * D_ + kvcol + c * 8;
            cp_async16(d,         khi + src);
            cp_async16(d + 8192,  klo + src);
            cp_async16(d + 16384, vhi + src);
            cp_async16(d + 24576, vlo + src);
        }
        cp_commit();
    };

    const int jmax = (q0 + 127) / 64;
    load_kv(0, 0);

    for (int j = 0; j <= jmax; j++) {
        const int st = j & 1;
        cp_wait<0>();
        __syncthreads();
        if (j < jmax) load_kv(j + 1, st ^ 1);

        if (64 * j <= q0 + w * 16 + 15) {
            const uint32_t kb = sb + (uint32_t)(st * 32768);
            const uint32_t vb = kb + 16384;

            float S[8][4];
            #pragma unroll
            for (int i = 0; i < 8; i++)
                #pragma unroll
                for (int jj = 0; jj < 4; jj++) S[i][jj] = 0.0f;

            #pragma unroll
            for (int ks = 0; ks < 4; ks++) {
                uint32_t fk[4][4];
                #pragma unroll
                for (int g16 = 0; g16 < 4; g16++) {
                    int r = g16 * 16 + b_nrow;
                    int c = 2 * ks + b_kc;
                    ldm_x4(fk[g16], kb + (uint32_t)(r * 128 + ((c ^ (r & 7)) << 4)));
                }
                #pragma unroll
                for (int nb = 0; nb < 8; nb++) {
                    const uint32_t* bf = &fk[nb >> 1][(nb & 1) * 2];
                    mma16816(S[nb], fqh[ks], bf);
                    mma16816(S[nb], fql[ks], bf);
                }
                #pragma unroll
                for (int g16 = 0; g16 < 4; g16++) {
                    int r = g16 * 16 + b_nrow;
                    int c = 2 * ks + b_kc;
                    ldm_x4(fk[g16], kb + 8192 + (uint32_t)(r * 128 + ((c ^ (r & 7)) << 4)));
                }
                #pragma unroll
                for (int nb = 0; nb < 8; nb++)
                    mma16816(S[nb], fqh[ks], &fk[nb >> 1][(nb & 1) * 2]);
            }

            if (64 * j + 63 > q0 + w * 16) {
                int colb = 64 * j + 2 * (L & 3);
                #pragma unroll
                for (int e = 0; e < 2; e++) {
                    int row = q0 + w * 16 + (L >> 2) + 8 * e;
                    #pragma unroll
                    for (int nb = 0; nb < 8; nb++) {
                        int c0 = colb + nb * 8;
                        if (c0 > row)     S[nb][2 * e]     = -1e30f;
                        if (c0 + 1 > row) S[nb][2 * e + 1] = -1e30f;
                    }
                }
            }

            #pragma unroll
            for (int e = 0; e < 2; e++) {
                float sum = 0.0f;
                #pragma unroll
                for (int nb = 0; nb < 8; nb++) {
                    float p0 = ex2(S[nb][2 * e]     - M_FIX);
                    float p1 = ex2(S[nb][2 * e + 1] - M_FIX);
                    S[nb][2 * e] = p0; S[nb][2 * e + 1] = p1;
                    sum += p0 + p1;
                }
                lsum[e] += sum;
            }

            uint32_t phi[8][2], plo[8][2];
            #pragma unroll
            for (int nb = 0; nb < 8; nb++) {
                uint32_t h0 = packbf(S[nb][0], S[nb][1]);
                uint32_t h1 = packbf(S[nb][2], S[nb][3]);
                phi[nb][0] = h0; phi[nb][1] = h1;
                plo[nb][0] = packbf(S[nb][0] - bflowf(h0), S[nb][1] - bfhighf(h0));
                plo[nb][1] = packbf(S[nb][2] - bflowf(h1), S[nb][3] - bfhighf(h1));
            }

            #pragma unroll
            for (int ks = 0; ks < 4; ks++) {
                uint32_t pah[4] = {phi[2 * ks][0], phi[2 * ks][1],
                                   phi[2 * ks + 1][0], phi[2 * ks + 1][1]};
                uint32_t pal[4] = {plo[2 * ks][0], plo[2 * ks][1],
                                   plo[2 * ks + 1][0], plo[2 * ks + 1][1]};
                uint32_t fv[4][4];
                #pragma unroll
                for (int dg = 0; dg < 4; dg++) {
                    int r = ks * 16 + vkrow;
                    int c = 2 * dg + vdch;
                    ldm_x4_t(fv[dg], vb + (uint32_t)(r * 128 + ((c ^ (r & 7)) << 4)));
                }
                #pragma unroll
                for (int db = 0; db < 8; db++) {
                    const uint32_t* bf = &fv[db >> 1][(db & 1) * 2];
                    mma16816(accO[db], pah, bf);
                    mma16816(accO[db], pal, bf);
                }
                #pragma unroll
                for (int dg = 0; dg < 4; dg++) {
                    int r = ks * 16 + vkrow;
                    int c = 2 * dg + vdch;
                    ldm_x4_t(fv[dg], vb + 8192 + (uint32_t)(r * 128 + ((c ^ (r & 7)) << 4)));
                }
                #pragma unroll
                for (int db = 0; db < 8; db++)
                    mma16816(accO[db], pah, &fv[db >> 1][(db & 1) * 2]);
            }
        }
        __syncthreads();
    }

    #pragma unroll
    for (int e = 0; e < 2; e++) {
        lsum[e] += __shfl_xor_sync(0xffffffffu, lsum[e], 1);
        lsum[e] += __shfl_xor_sync(0xffffffffu, lsum[e], 2);
    }
    #pragma unroll
    for (int e = 0; e < 2; e++) {
        int row = q0 + w * 16 + (L >> 2) + 8 * e;
        float inv = __fdividef(1.0f, lsum[e]);
        size_t rb = ((size_t)b * S_ + row) * D_ + h * HD_;
        #pragma unroll
        for (int db = 0; db < 8; db++) {
            int col = db * 8 + 2 * (L & 3);
            float f0 = accO[db][2 * e]     * inv;
            float f1 = accO[db][2 * e + 1] * inv;
            uint32_t hp = packbf(f0, f1);
            uint32_t lp = packbf(f0 - bflowf(hp), f1 - bfhighf(hp));
            *(uint32_t*)&ohi[rb + col] = hp;
            *(uint32_t*)&olo[rb + col] = lp;
        }
    }
}

// ---------------------------------------------------------------------------
// kernel_launch
// ---------------------------------------------------------------------------
extern "C" void kernel_launch(void* const* d_in, const int* in_sizes, int n_in,
                              void* d_out, int out_size)
{
    const float* x  = (const float*)d_in[0];
    const float* Wq = (const float*)d_in[1];
    const float* bq = (const float*)d_in[2];
    const float* Wk = (const float*)d_in[3];
    const float* bk = (const float*)d_in[4];
    const float* Wv = (const float*)d_in[5];
    const float* bv = (const float*)d_in[6];
    const float* Wo = (const float*)d_in[7];
    const float* bo = (const float*)d_in[8];
    float* out = (float*)d_out;

    __nv_bfloat16 *qhi, *qlo, *khi, *klo, *vhi, *vlo, *ohi, *olo;
    __nv_bfloat16 *xhi, *xlo, *wThi, *wTlo;
    cudaGetSymbolAddress((void**)&qhi, g_qhi);
    cudaGetSymbolAddress((void**)&qlo, g_qlo);
    cudaGetSymbolAddress((void**)&khi, g_khi);
    cudaGetSymbolAddress((void**)&klo, g_klo);
    cudaGetSymbolAddress((void**)&vhi, g_vhi);
    cudaGetSymbolAddress((void**)&vlo, g_vlo);
    cudaGetSymbolAddress((void**)&ohi, g_ohi);
    cudaGetSymbolAddress((void**)&olo, g_olo);
    cudaGetSymbolAddress((void**)&xhi, g_xhi);
    cudaGetSymbolAddress((void**)&xlo, g_xlo);
    cudaGetSymbolAddress((void**)&wThi, g_wThi);
    cudaGetSymbolAddress((void**)&wTlo, g_wTlo);

    cudaFuncSetAttribute(attn_mma_kernel,
                         cudaFuncAttributeMaxDynamicSharedMemorySize, AT_SMEM);
    cudaFuncSetAttribute(gemm_qkv_kernel,
                         cudaFuncAttributeMaxDynamicSharedMemorySize, GEMM_SMEM);
    cudaFuncSetAttribute(gemm_o_kernel,
                         cudaFuncAttributeMaxDynamicSharedMemorySize, GEMM_SMEM);

    const size_t WSZ = (size_t)N_ * K_;

    prep_kernel<<<12288, 256>>>(x, xhi, xlo, Wq, Wk, Wv, Wo, wThi, wTlo);

    const float qscale = 0.125f * 1.4426950408889634f;

    gemm_qkv_kernel<<<GEMM_GRID, 256, GEMM_SMEM>>>(xhi, xlo, wThi, wTlo,
                                                   bq, bk, bv,
                                                   qhi, qlo, khi, klo, vhi, vlo,
                                                   qscale);

    dim3 ag(S_ / 128, B_ * H_);
    attn_mma_kernel<<<ag, 256, AT_SMEM>>>(qhi, qlo, khi, klo, vhi, vlo, ohi, olo);

    gemm_o_kernel<<<GEMM_GRID, 256, GEMM_SMEM>>>(ohi, olo, wThi + 3 * WSZ,
                                                 wTlo + 3 * WSZ, bo, out);
}

// round 16
// speedup vs baseline: 1.0042x; 1.0042x over previous
#include <cuda_runtime.h>
#include <cuda_bf16.h>
#include <cstdint>
#include <math.h>

// Problem constants
#define B_   4
#define S_   2048
#define D_   1024
#define H_   16
#define HD_  64
#define M_   (B_ * S_)   // 8192 rows
#define K_   1024
#define N_   1024

// ---------------------------------------------------------------------------
// Scratch (static __device__; allocation is forbidden)
// ---------------------------------------------------------------------------
__device__ __nv_bfloat16 g_qhi[(size_t)M_ * D_];
__device__ __nv_bfloat16 g_qlo[(size_t)M_ * D_];
__device__ __nv_bfloat16 g_khi[(size_t)M_ * D_];
__device__ __nv_bfloat16 g_klo[(size_t)M_ * D_];
__device__ __nv_bfloat16 g_vhi[(size_t)M_ * D_];
__device__ __nv_bfloat16 g_vlo[(size_t)M_ * D_];
__device__ __nv_bfloat16 g_ohi[(size_t)M_ * D_];
__device__ __nv_bfloat16 g_olo[(size_t)M_ * D_];
__device__ __nv_bfloat16 g_xhi[(size_t)M_ * D_];
__device__ __nv_bfloat16 g_xlo[(size_t)M_ * D_];
// transposed split weights: [4][N][K]  (order: q,k,v,o)
__device__ __nv_bfloat16 g_wThi[(size_t)4 * N_ * K_];
__device__ __nv_bfloat16 g_wTlo[(size_t)4 * N_ * K_];

// ---------------------------------------------------------------------------
// helpers
// ---------------------------------------------------------------------------
__device__ __forceinline__ uint32_t smem_u32(const void* p) {
    uint32_t a;
    asm("{ .reg .u64 t; cvta.to.shared.u64 t, %1; cvt.u32.u64 %0, t; }"
        : "=r"(a) : "l"(p));
    return a;
}
__device__ __forceinline__ void cp_async16(uint32_t dst, const void* src) {
    asm volatile("cp.async.cg.shared.global [%0], [%1], 16;"
                 :: "r"(dst), "l"(src) : "memory");
}
__device__ __forceinline__ void cp_commit() {
    asm volatile("cp.async.commit_group;" ::: "memory");
}
template <int N>
__device__ __forceinline__ void cp_wait() {
    asm volatile("cp.async.wait_group %0;" :: "n"(N) : "memory");
}
__device__ __forceinline__ void ldm_x4(uint32_t (&r)[4], uint32_t addr) {
    asm volatile("ldmatrix.sync.aligned.m8n8.x4.shared.b16 {%0,%1,%2,%3}, [%4];"
                 : "=r"(r[0]), "=r"(r[1]), "=r"(r[2]), "=r"(r[3]) : "r"(addr));
}
__device__ __forceinline__ void ldm_x4_t(uint32_t (&r)[4], uint32_t addr) {
    asm volatile("ldmatrix.sync.aligned.m8n8.x4.trans.shared.b16 {%0,%1,%2,%3}, [%4];"
                 : "=r"(r[0]), "=r"(r[1]), "=r"(r[2]), "=r"(r[3]) : "r"(addr));
}
__device__ __forceinline__ void mma16816(float* d, const uint32_t* a, const uint32_t* b) {
    asm volatile(
        "mma.sync.aligned.m16n8k16.row.col.f32.bf16.bf16.f32 "
        "{%0,%1,%2,%3}, {%4,%5,%6,%7}, {%8,%9}, {%0,%1,%2,%3};"
        : "+f"(d[0]), "+f"(d[1]), "+f"(d[2]), "+f"(d[3])
        : "r"(a[0]), "r"(a[1]), "r"(a[2]), "r"(a[3]), "r"(b[0]), "r"(b[1]));
}
__device__ __forceinline__ float ex2(float x) {
    float y;
    asm("ex2.approx.f32 %0, %1;" : "=f"(y) : "f"(x));
    return y;
}
__device__ __forceinline__ uint32_t packbf(float lo, float hi) {
    uint32_t d;
    asm("cvt.rn.bf16x2.f32 %0, %1, %2;" : "=r"(d) : "f"(hi), "f"(lo));
    return d;
}
__device__ __forceinline__ float bflowf(uint32_t p)  { return __uint_as_float(p << 16); }
__device__ __forceinline__ float bfhighf(uint32_t p) { return __uint_as_float(p & 0xFFFF0000u); }

// ---------------------------------------------------------------------------
// Fused prep: blocks [0, 8192) split x; blocks [8192, 12288) split+transpose W.
// ---------------------------------------------------------------------------
__global__ __launch_bounds__(256)
void prep_kernel(const float* __restrict__ x,
                 __nv_bfloat16* __restrict__ xhi,
                 __nv_bfloat16* __restrict__ xlo,
                 const float* __restrict__ Wq,
                 const float* __restrict__ Wk,
                 const float* __restrict__ Wv,
                 const float* __restrict__ Wo,
                 __nv_bfloat16* __restrict__ wThi,
                 __nv_bfloat16* __restrict__ wTlo)
{
    const int bx = blockIdx.x;
    if (bx < 8192) {
        int i = bx * 256 + threadIdx.x;
        float4 v = ((const float4*)x)[i];
        uint32_t h0 = packbf(v.x, v.y);
        uint32_t h1 = packbf(v.z, v.w);
        uint32_t l0 = packbf(v.x - bflowf(h0), v.y - bfhighf(h0));
        uint32_t l1 = packbf(v.z - bflowf(h1), v.w - bfhighf(h1));
        ((uint32_t*)xhi)[i * 2 + 0] = h0;
        ((uint32_t*)xhi)[i * 2 + 1] = h1;
        ((uint32_t*)xlo)[i * 2 + 0] = l0;
        ((uint32_t*)xlo)[i * 2 + 1] = l1;
    } else {
        __shared__ float t[32][33];
        const int u    = bx - 8192;
        const int widx = u >> 10;
        const int tile = u & 1023;
        const int n0 = (tile & 31) * 32;
        const int k0 = (tile >> 5) * 32;
        const float* W = (widx == 0) ? Wq : (widx == 1) ? Wk : (widx == 2) ? Wv : Wo;
        __nv_bfloat16* hiT = wThi + (size_t)widx * N_ * K_;
        __nv_bfloat16* loT = wTlo + (size_t)widx * N_ * K_;
        const int tx = threadIdx.x & 31;
        const int ty = threadIdx.x >> 5;
        #pragma unroll
        for (int i = 0; i < 4; i++) {
            int kr = ty + i * 8;
            t[kr][tx] = W[(size_t)(k0 + kr) * N_ + n0 + tx];
        }
        __syncthreads();
        #pragma unroll
        for (int i = 0; i < 4; i++) {
            int nr = ty + i * 8;
            float v = t[tx][nr];
            __nv_bfloat16 h = __float2bfloat16_rn(v);
            size_t idx = (size_t)(n0 + nr) * K_ + k0 + tx;
            hiT[idx] = h;
            loT[idx] = __float2bfloat16_rn(v - __bfloat162float(h));
        }
    }
}

// ---------------------------------------------------------------------------
// HMMA split-bf16 GEMM core (3-stage, 1 barrier/chunk). R9 configuration.
// ---------------------------------------------------------------------------
#define GBK 32
static constexpr uint32_t TILEB  = 128 * GBK * 2;   // 8192
static constexpr uint32_t STAGEB = 4 * TILEB;       // 32768
#define GEMM_SMEM (3 * STAGEB)                      // 98304

__device__ __forceinline__ uint32_t swz64(int r, int c) {
    return (uint32_t)(r * 64 + ((c ^ ((r >> 1) & 3)) << 4));
}

template <bool SPLIT_OUT>
__device__ __forceinline__
void gemm_core(const __nv_bfloat16* __restrict__ Ahi,
               const __nv_bfloat16* __restrict__ Alo,
               const __nv_bfloat16* __restrict__ BhiT,
               const __nv_bfloat16* __restrict__ BloT,
               const float* __restrict__ bias,
               float* __restrict__ C,
               __nv_bfloat16* __restrict__ Chi,
               __nv_bfloat16* __restrict__ Clo,
               float scale, int bm, int bn)
{
    extern __shared__ char gsm[];
    const uint32_t sb = smem_u32(gsm);
    const int tid = threadIdx.x;
    const int L   = tid & 31;
    const int wid = tid >> 5;
    const int warp_m = wid >> 2;
    const int warp_n = wid & 3;

    const int r0 = tid >> 2,         c0 = tid & 3;
    const int r1 = (tid + 256) >> 2, c1 = (tid + 256) & 3;
    const uint32_t d0 = swz64(r0, c0);
    const uint32_t d1 = swz64(r1, c1);

    const __nv_bfloat16* srcAhi0 = Ahi + (size_t)(bm + r0) * K_ + c0 * 8;
    const __nv_bfloat16* srcAlo0 = Alo + (size_t)(bm + r0) * K_ + c0 * 8;
    const __nv_bfloat16* srcBhi0 = BhiT + (size_t)(bn + r0) * K_ + c0 * 8;
    const __nv_bfloat16* srcBlo0 = BloT + (size_t)(bn + r0) * K_ + c0 * 8;
    const __nv_bfloat16* srcAhi1 = Ahi + (size_t)(bm + r1) * K_ + c1 * 8;
    const __nv_bfloat16* srcAlo1 = Alo + (size_t)(bm + r1) * K_ + c1 * 8;
    const __nv_bfloat16* srcBhi1 = BhiT + (size_t)(bn + r1) * K_ + c1 * 8;
    const __nv_bfloat16* srcBlo1 = BloT + (size_t)(bn + r1) * K_ + c1 * 8;

    const int a_mrow = (L & 7) | (((L >> 3) & 1) << 3);
    const int a_kc   = (L >> 4) & 1;
    const int b_nrow = (L & 7) | (((L >> 4) & 1) << 3);
    const int b_kc   = (L >> 3) & 1;

    float acc[4][4][4];
    #pragma unroll
    for (int mi = 0; mi < 4; mi++)
        #pragma unroll
        for (int ni = 0; ni < 4; ni++)
            #pragma unroll
            for (int j = 0; j < 4; j++)
                acc[mi][ni][j] = 0.0f;

    auto load_stage = [&](int ch, int st) {
        const int ko = ch * GBK;
        const uint32_t s = sb + st * STAGEB;
        cp_async16(s + d0,              srcAhi0 + ko);
        cp_async16(s + TILEB + d0,      srcAlo0 + ko);
        cp_async16(s + 2 * TILEB + d0,  srcBhi0 + ko);
        cp_async16(s + 3 * TILEB + d0,  srcBlo0 + ko);
        cp_async16(s + d1,              srcAhi1 + ko);
        cp_async16(s + TILEB + d1,      srcAlo1 + ko);
        cp_async16(s + 2 * TILEB + d1,  srcBhi1 + ko);
        cp_async16(s + 3 * TILEB + d1,  srcBlo1 + ko);
        cp_commit();
    };

    load_stage(0, 0);
    load_stage(1, 1);

    const int NCH = K_ / GBK;
    int st = 0;
    for (int ch = 0; ch < NCH; ch++) {
        if (ch + 1 < NCH) { cp_wait<1>(); } else { cp_wait<0>(); }
        __syncthreads();
        if (ch + 2 < NCH) {
            int st2 = st + 2; if (st2 >= 3) st2 -= 3;
            load_stage(ch + 2, st2);
        }

        const uint32_t s = sb + st * STAGEB;
        #pragma unroll
        for (int ks = 0; ks < 2; ks++) {
            uint32_t ahi[4][4], alo[4][4], bhi[2][4], blo[2][4];
            const int ca = ks * 2 + a_kc;
            #pragma unroll
            for (int mi = 0; mi < 4; mi++) {
                int r = warp_m * 64 + mi * 16 + a_mrow;
                uint32_t o = swz64(r, ca);
                ldm_x4(ahi[mi], s + o);
                ldm_x4(alo[mi], s + TILEB + o);
            }
            const int cb = ks * 2 + b_kc;
            #pragma unroll
            for (int j = 0; j < 2; j++) {
                int r = warp_n * 32 + j * 16 + b_nrow;
                uint32_t o = swz64(r, cb);
                ldm_x4(bhi[j], s + 2 * TILEB + o);
                ldm_x4(blo[j], s + 3 * TILEB + o);
            }
            #pragma unroll
            for (int mi = 0; mi < 4; mi++) {
                #pragma unroll
                for (int ni = 0; ni < 4; ni++) {
                    const uint32_t* bh = &bhi[ni >> 1][(ni & 1) * 2];
                    const uint32_t* bl = &blo[ni >> 1][(ni & 1) * 2];
                    mma16816(acc[mi][ni], ahi[mi], bh);
                    mma16816(acc[mi][ni], ahi[mi], bl);
                    mma16816(acc[mi][ni], alo[mi], bh);
                }
            }
        }
        st = st + 1; if (st >= 3) st = 0;
    }

    const int g  = L >> 2;
    const int tg = L & 3;
    #pragma unroll
    for (int mi = 0; mi < 4; mi++) {
        int row0 = bm + warp_m * 64 + mi * 16 + g;
        #pragma unroll
        for (int ni = 0; ni < 4; ni++) {
            int col = bn + warp_n * 32 + ni * 8 + tg * 2;
            float b0 = bias[col], b1 = bias[col + 1];
            float r00 = (acc[mi][ni][0] + b0) * scale;
            float r01 = (acc[mi][ni][1] + b1) * scale;
            float r10 = (acc[mi][ni][2] + b0) * scale;
            float r11 = (acc[mi][ni][3] + b1) * scale;
            if (SPLIT_OUT) {
                uint32_t h0 = packbf(r00, r01);
                uint32_t l0 = packbf(r00 - bflowf(h0), r01 - bfhighf(h0));
                uint32_t h1 = packbf(r10, r11);
                uint32_t l1 = packbf(r10 - bflowf(h1), r11 - bfhighf(h1));
                *(uint32_t*)&Chi[(size_t)row0 * N_ + col] = h0;
                *(uint32_t*)&Clo[(size_t)row0 * N_ + col] = l0;
                *(uint32_t*)&Chi[(size_t)(row0 + 8) * N_ + col] = h1;
                *(uint32_t*)&Clo[(size_t)(row0 + 8) * N_ + col] = l1;
            } else {
                float2 v0 = {r00, r01}, v1 = {r10, r11};
                *(float2*)&C[(size_t)row0 * N_ + col] = v0;
                *(float2*)&C[(size_t)(row0 + 8) * N_ + col] = v1;
            }
        }
    }
}

// Fused Q/K/V projection: grid (24, 64). n-block 0-7 -> Q, 8-15 -> K, 16-23 -> V.
__global__ __launch_bounds__(256)
void gemm_qkv_kernel(const __nv_bfloat16* __restrict__ xhi,
                     const __nv_bfloat16* __restrict__ xlo,
                     const __nv_bfloat16* __restrict__ wThi,
                     const __nv_bfloat16* __restrict__ wTlo,
                     const float* __restrict__ bq,
                     const float* __restrict__ bk,
                     const float* __restrict__ bv,
                     __nv_bfloat16* __restrict__ qhi, __nv_bfloat16* __restrict__ qlo,
                     __nv_bfloat16* __restrict__ khi, __nv_bfloat16* __restrict__ klo,
                     __nv_bfloat16* __restrict__ vhi, __nv_bfloat16* __restrict__ vlo,
                     float qscale)
{
    const int which = blockIdx.x >> 3;
    const int bn = (blockIdx.x & 7) * 128;
    const int bm = blockIdx.y * 128;
    const size_t WSZ = (size_t)N_ * K_;

    const __nv_bfloat16* Bhi = wThi + (size_t)which * WSZ;
    const __nv_bfloat16* Blo = wTlo + (size_t)which * WSZ;
    const float* bias = (which == 0) ? bq : (which == 1) ? bk : bv;
    __nv_bfloat16* Chi = (which == 0) ? qhi : (which == 1) ? khi : vhi;
    __nv_bfloat16* Clo = (which == 0) ? qlo : (which == 1) ? klo : vlo;
    const float scale = (which == 0) ? qscale : 1.0f;

    gemm_core<true>(xhi, xlo, Bhi, Blo, bias, nullptr, Chi, Clo, scale, bm, bn);
}

// Output projection: grid (8, 64), fp32 out.
__global__ __launch_bounds__(256)
void gemm_o_kernel(const __nv_bfloat16* __restrict__ ohi,
                   const __nv_bfloat16* __restrict__ olo,
                   const __nv_bfloat16* __restrict__ wThiO,
                   const __nv_bfloat16* __restrict__ wTloO,
                   const float* __restrict__ bo,
                   float* __restrict__ out)
{
    gemm_core<false>(ohi, olo, wThiO, wTloO, bo, out, nullptr, nullptr, 1.0f,
                     blockIdx.y * 128, blockIdx.x * 128);
}

// ---------------------------------------------------------------------------
// Tensor-core causal flash attention, split-bf16, FIXED-MAX exp2 softmax.
// __launch_bounds__(256, 2): cap regs at 128 -> 2 CTAs/SM to hide
// softmax/LDSM bubbles via cross-CTA interleave. smem 64KB x 2 fits.
// ---------------------------------------------------------------------------
#define AT_SMEM 65536
#define M_FIX 24.0f

__global__ __launch_bounds__(256, 2)
void attn_mma_kernel(const __nv_bfloat16* __restrict__ qhi,
                     const __nv_bfloat16* __restrict__ qlo,
                     const __nv_bfloat16* __restrict__ khi,
                     const __nv_bfloat16* __restrict__ klo,
                     const __nv_bfloat16* __restrict__ vhi,
                     const __nv_bfloat16* __restrict__ vlo,
                     __nv_bfloat16* __restrict__ ohi,
                     __nv_bfloat16* __restrict__ olo)
{
    extern __shared__ char sm[];
    const uint32_t sb = smem_u32(sm);
    const int tid = threadIdx.x;
    const int L   = tid & 31;
    const int w   = tid >> 5;
    const int bh  = blockIdx.y;
    const int b   = bh >> 4;
    const int h   = bh & 15;
    const int q0  = (int)(gridDim.x - 1 - blockIdx.x) * 128;

    #pragma unroll
    for (int i = 0; i < 4; i++) {
        int u = i * 256 + tid;
        int r = u >> 3;
        int c = u & 7;
        uint32_t d = sb + (uint32_t)(r * 128 + ((c ^ (r & 7)) << 4));
        size_t src = ((size_t)b * S_ + q0 + r) * D_ + h * HD_ + c * 8;
        cp_async16(d,         qhi + src);
        cp_async16(d + 16384, qlo + src);
    }
    cp_commit();
    cp_wait<0>();
    __syncthreads();

    const int a_mrow = (L & 7) | (((L >> 3) & 1) << 3);
    const int a_kc   = (L >> 4) & 1;
    uint32_t fqh[4][4], fql[4][4];
    #pragma unroll
    for (int ks = 0; ks < 4; ks++) {
        int r = w * 16 + a_mrow;
        int c = 2 * ks + a_kc;
        uint32_t addr = sb + (uint32_t)(r * 128 + ((c ^ (r & 7)) << 4));
        ldm_x4(fqh[ks], addr);
        ldm_x4(fql[ks], addr + 16384);
    }
    __syncthreads();

    const int b_nrow = (L & 7) | (((L >> 4) & 1) << 3);
    const int b_kc   = (L >> 3) & 1;
    const int vkrow  = L & 15;
    const int vdch   = (L >> 4) & 1;

    float accO[8][4];
    #pragma unroll
    for (int i = 0; i < 8; i++)
        #pragma unroll
        for (int j = 0; j < 4; j++) accO[i][j] = 0.0f;
    float lsum[2] = {0.0f, 0.0f};

    const size_t kvcol = (size_t)h * HD_;

    auto load_kv = [&](int j, int st) {
        uint32_t base = sb + (uint32_t)(st * 32768);
        size_t row0 = (size_t)b * S_ + j * 64;
        #pragma unroll
        for (int i = 0; i < 2; i++) {
            int u = i * 256 + tid;
            int r = u >> 3;
            int c = u & 7;
            uint32_t d = base + (uint32_t)(r * 128 + ((c ^ (r & 7)) << 4));
            size_t src = (row0 + r) * D_ + kvcol + c * 8;
            cp_async16(d,         khi + src);
            cp_async16(d + 8192,  klo + src);
            cp_async16(d + 16384, vhi + src);
            cp_async16(d + 24576, vlo + src);
        }
        cp_commit();
    };

    const int jmax = (q0 + 127) / 64;
    load_kv(0, 0);

    for (int j = 0; j <= jmax; j++) {
        const int st = j & 1;
        cp_wait<0>();
        __syncthreads();
        if (j < jmax) load_kv(j + 1, st ^ 1);

        if (64 * j <= q0 + w * 16 + 15) {
            const uint32_t kb = sb + (uint32_t)(st * 32768);
            const uint32_t vb = kb + 16384;

            float S[8][4];
            #pragma unroll
            for (int i = 0; i < 8; i++)
                #pragma unroll
                for (int jj = 0; jj < 4; jj++) S[i][jj] = 0.0f;

            #pragma unroll
            for (int ks = 0; ks < 4; ks++) {
                uint32_t fk[4][4];
                #pragma unroll
                for (int g16 = 0; g16 < 4; g16++) {
                    int r = g16 * 16 + b_nrow;
                    int c = 2 * ks + b_kc;
                    ldm_x4(fk[g16], kb + (uint32_t)(r * 128 + ((c ^ (r & 7)) << 4)));
                }
                #pragma unroll
                for (int nb = 0; nb < 8; nb++) {
                    const uint32_t* bf = &fk[nb >> 1][(nb & 1) * 2];
                    mma16816(S[nb], fqh[ks], bf);
                    mma16816(S[nb], fql[ks], bf);
                }
                #pragma unroll
                for (int g16 = 0; g16 < 4; g16++) {
                    int r = g16 * 16 + b_nrow;
                    int c = 2 * ks + b_kc;
                    ldm_x4(fk[g16], kb + 8192 + (uint32_t)(r * 128 + ((c ^ (r & 7)) << 4)));
                }
                #pragma unroll
                for (int nb = 0; nb < 8; nb++)
                    mma16816(S[nb], fqh[ks], &fk[nb >> 1][(nb & 1) * 2]);
            }

            if (64 * j + 63 > q0 + w * 16) {
                int colb = 64 * j + 2 * (L & 3);
                #pragma unroll
                for (int e = 0; e < 2; e++) {
                    int row = q0 + w * 16 + (L >> 2) + 8 * e;
                    #pragma unroll
                    for (int nb = 0; nb < 8; nb++) {
                        int c0 = colb + nb * 8;
                        if (c0 > row)     S[nb][2 * e]     = -1e30f;
                        if (c0 + 1 > row) S[nb][2 * e + 1] = -1e30f;
                    }
                }
            }

            #pragma unroll
            for (int e = 0; e < 2; e++) {
                float sum = 0.0f;
                #pragma unroll
                for (int nb = 0; nb < 8; nb++) {
                    float p0 = ex2(S[nb][2 * e]     - M_FIX);
                    float p1 = ex2(S[nb][2 * e + 1] - M_FIX);
                    S[nb][2 * e] = p0; S[nb][2 * e + 1] = p1;
                    sum += p0 + p1;
                }
                lsum[e] += sum;
            }

            uint32_t phi[8][2], plo[8][2];
            #pragma unroll
            for (int nb = 0; nb < 8; nb++) {
                uint32_t h0 = packbf(S[nb][0], S[nb][1]);
                uint32_t h1 = packbf(S[nb][2], S[nb][3]);
                phi[nb][0] = h0; phi[nb][1] = h1;
                plo[nb][0] = packbf(S[nb][0] - bflowf(h0), S[nb][1] - bfhighf(h0));
                plo[nb][1] = packbf(S[nb][2] - bflowf(h1), S[nb][3] - bfhighf(h1));
            }

            #pragma unroll
            for (int ks = 0; ks < 4; ks++) {
                uint32_t pah[4] = {phi[2 * ks][0], phi[2 * ks][1],
                                   phi[2 * ks + 1][0], phi[2 * ks + 1][1]};
                uint32_t pal[4] = {plo[2 * ks][0], plo[2 * ks][1],
                                   plo[2 * ks + 1][0], plo[2 * ks + 1][1]};
                uint32_t fv[4][4];
                #pragma unroll
                for (int dg = 0; dg < 4; dg++) {
                    int r = ks * 16 + vkrow;
                    int c = 2 * dg + vdch;
                    ldm_x4_t(fv[dg], vb + (uint32_t)(r * 128 + ((c ^ (r & 7)) << 4)));
                }
                #pragma unroll
                for (int db = 0; db < 8; db++) {
                    const uint32_t* bf = &fv[db >> 1][(db & 1) * 2];
                    mma16816(accO[db], pah, bf);
                    mma16816(accO[db], pal, bf);
                }
                #pragma unroll
                for (int dg = 0; dg < 4; dg++) {
                    int r = ks * 16 + vkrow;
                    int c = 2 * dg + vdch;
                    ldm_x4_t(fv[dg], vb + 8192 + (uint32_t)(r * 128 + ((c ^ (r & 7)) << 4)));
                }
                #pragma unroll
                for (int db = 0; db < 8; db++)
                    mma16816(accO[db], pah, &fv[db >> 1][(db & 1) * 2]);
            }
        }
        __syncthreads();
    }

    #pragma unroll
    for (int e = 0; e < 2; e++) {
        lsum[e] += __shfl_xor_sync(0xffffffffu, lsum[e], 1);
        lsum[e] += __shfl_xor_sync(0xffffffffu, lsum[e], 2);
    }
    #pragma unroll
    for (int e = 0; e < 2; e++) {
        int row = q0 + w * 16 + (L >> 2) + 8 * e;
        float inv = __fdividef(1.0f, lsum[e]);
        size_t rb = ((size_t)b * S_ + row) * D_ + h * HD_;
        #pragma unroll
        for (int db = 0; db < 8; db++) {
            int col = db * 8 + 2 * (L & 3);
            float f0 = accO[db][2 * e]     * inv;
            float f1 = accO[db][2 * e + 1] * inv;
            uint32_t hp = packbf(f0, f1);
            uint32_t lp = packbf(f0 - bflowf(hp), f1 - bfhighf(hp));
            *(uint32_t*)&ohi[rb + col] = hp;
            *(uint32_t*)&olo[rb + col] = lp;
        }
    }
}

// ---------------------------------------------------------------------------
// kernel_launch
// ---------------------------------------------------------------------------
extern "C" void kernel_launch(void* const* d_in, const int* in_sizes, int n_in,
                              void* d_out, int out_size)
{
    const float* x  = (const float*)d_in[0];
    const float* Wq = (const float*)d_in[1];
    const float* bq = (const float*)d_in[2];
    const float* Wk = (const float*)d_in[3];
    const float* bk = (const float*)d_in[4];
    const float* Wv = (const float*)d_in[5];
    const float* bv = (const float*)d_in[6];
    const float* Wo = (const float*)d_in[7];
    const float* bo = (const float*)d_in[8];
    float* out = (float*)d_out;

    __nv_bfloat16 *qhi, *qlo, *khi, *klo, *vhi, *vlo, *ohi, *olo;
    __nv_bfloat16 *xhi, *xlo, *wThi, *wTlo;
    cudaGetSymbolAddress((void**)&qhi, g_qhi);
    cudaGetSymbolAddress((void**)&qlo, g_qlo);
    cudaGetSymbolAddress((void**)&khi, g_khi);
    cudaGetSymbolAddress((void**)&klo, g_klo);
    cudaGetSymbolAddress((void**)&vhi, g_vhi);
    cudaGetSymbolAddress((void**)&vlo, g_vlo);
    cudaGetSymbolAddress((void**)&ohi, g_ohi);
    cudaGetSymbolAddress((void**)&olo, g_olo);
    cudaGetSymbolAddress((void**)&xhi, g_xhi);
    cudaGetSymbolAddress((void**)&xlo, g_xlo);
    cudaGetSymbolAddress((void**)&wThi, g_wThi);
    cudaGetSymbolAddress((void**)&wTlo, g_wTlo);

    cudaFuncSetAttribute(attn_mma_kernel,
                         cudaFuncAttributeMaxDynamicSharedMemorySize, AT_SMEM);
    cudaFuncSetAttribute(gemm_qkv_kernel,
                         cudaFuncAttributeMaxDynamicSharedMemorySize, GEMM_SMEM);
    cudaFuncSetAttribute(gemm_o_kernel,
                         cudaFuncAttributeMaxDynamicSharedMemorySize, GEMM_SMEM);

    const size_t WSZ = (size_t)N_ * K_;

    prep_kernel<<<12288, 256>>>(x, xhi, xlo, Wq, Wk, Wv, Wo, wThi, wTlo);

    const float qscale = 0.125f * 1.4426950408889634f;

    dim3 gqkv(24, M_ / 128);
    gemm_qkv_kernel<<<gqkv, 256, GEMM_SMEM>>>(xhi, xlo, wThi, wTlo,
                                              bq, bk, bv,
                                              qhi, qlo, khi, klo, vhi, vlo, qscale);

    dim3 ag(S_ / 128, B_ * H_);
    attn_mma_kernel<<<ag, 256, AT_SMEM>>>(qhi, qlo, khi, klo, vhi, vlo, ohi, olo);

    dim3 go(N_ / 128, M_ / 128);
    gemm_o_kernel<<<go, 256, GEMM_SMEM>>>(ohi, olo, wThi + 3 * WSZ, wTlo + 3 * WSZ,
                                          bo, out);
}